// round 6
// baseline (speedup 1.0000x reference)
#include <cuda_runtime.h>
#include <math.h>

#define NN 100000
#define NE 1600000
#define EMBD 64
#define EPSBN 1e-5f

// ---------------- scratch (static device globals; no allocation) ----------------
__device__ __align__(16) float g_p[(size_t)NN * EMBD];
__device__ __align__(16) float g_q[(size_t)NN * EMBD];
__device__ __align__(16) float g_aggr[(size_t)NN * EMBD];
__device__ __align__(16) float g_y2[(size_t)NE * EMBD];     // 409.6 MB
__device__ __align__(16) float g_y3[(size_t)NN * EMBD];
__device__ __align__(16) float g_y4[(size_t)NN * EMBD];
__device__ int g_src[NE];
__device__ int g_dst[NE];
__device__ float g_Cp[4 * EMBD];
__device__ float g_Cq[4 * EMBD];
__device__ float g_Cu[4 * EMBD];
__device__ float g_cb1[EMBD];
__device__ float g_cbu[EMBD];
__device__ float g_stats[8 * EMBD];   // (sum, sumsq) x 4 BN layers  (512 floats)
__device__ float g_bn[8 * EMBD];      // (a, s) x 4 BN layers
__device__ int g_is64;

// ---------------- edge_index dtype detection (int64 vs int32) ----------------
__global__ void k_detect(const unsigned int* w) {
    __shared__ int bad;
    if (threadIdx.x == 0) bad = 0;
    __syncthreads();
    // If data is int64 (values < 2^31), every odd 32-bit word is 0.
    // If data is int32 uniform in [0,100000), P(2048 zeros) ~ 0.
    for (int i = 1 + 2 * threadIdx.x; i < 4096; i += 2 * blockDim.x)
        if (w[i] != 0u) bad = 1;
    __syncthreads();
    if (threadIdx.x == 0) g_is64 = bad ? 0 : 1;
}

__global__ void k_conv(const void* ei) {
    int e = blockIdx.x * blockDim.x + threadIdx.x;
    if (e >= NE) return;
    if (g_is64) {
        const long long* p = (const long long*)ei;
        g_src[e] = (int)p[e];
        g_dst[e] = (int)p[(size_t)NE + e];
    } else {
        const int* p = (const int*)ei;
        g_src[e] = p[e];
        g_dst[e] = p[NE + e];
    }
}

// ---------------- zeroing (aggr + ALL 512 stats entries) ----------------
__global__ void k_zero() {
    size_t i = (size_t)blockIdx.x * blockDim.x + threadIdx.x;
    size_t total = (size_t)NN * EMBD;
    for (; i < total; i += (size_t)gridDim.x * blockDim.x) g_aggr[i] = 0.f;
    // 8*EMBD = 512 floats; blockDim = 256 -> use the first TWO blocks.
    if (blockIdx.x < 2) g_stats[blockIdx.x * 256 + threadIdx.x] = 0.f;
}

// ---------------- composite 4x64 matrices (fold W_in through the first linears) ----------------
__global__ void k_pre(const float* W_in, const float* b_in,
                      const float* mW1, const float* mb1,
                      const float* uW1, const float* ub1) {
    int tid = threadIdx.x;          // 256 threads: (f = tid/64 in 0..3, c = tid%64)
    int f = tid >> 6, c = tid & 63;
    float sp = 0.f, sq = 0.f, su = 0.f;
    for (int k = 0; k < EMBD; k++) {
        float w = W_in[f * EMBD + k];
        sp += w * mW1[k * EMBD + c];
        sq += w * mW1[(EMBD + k) * EMBD + c];
        su += w * uW1[k * EMBD + c];
    }
    g_Cp[tid] = sp; g_Cq[tid] = sq; g_Cu[tid] = su;
    if (f == 0) {
        float s1 = mb1[c], s2 = ub1[c];
        for (int k = 0; k < EMBD; k++) {
            float b = b_in[k];
            s1 += b * (mW1[k * EMBD + c] + mW1[(EMBD + k) * EMBD + c]);
            s2 += b * uW1[k * EMBD + c];
        }
        g_cb1[c] = s1; g_cbu[c] = s2;
    }
}

// ---------------- per-node p,q (h @ mW1_top / mW1_bot, via composites) ----------------
__global__ void k_pq(const float* pos, const float* vel) {
    int i = blockIdx.x * blockDim.x + threadIdx.x;
    if (i >= NN * EMBD) return;
    int n = i >> 6, c = i & 63;
    float x0 = pos[2 * n], x1 = pos[2 * n + 1];
    float x2 = vel[2 * n], x3 = vel[2 * n + 1];
    g_p[i] = x0 * g_Cp[c] + x1 * g_Cp[64 + c] + x2 * g_Cp[128 + c] + x3 * g_Cp[192 + c];
    g_q[i] = x0 * g_Cq[c] + x1 * g_Cq[64 + c] + x2 * g_Cq[128 + c] + x3 * g_Cq[192 + c];
}

// ---------------- BN1 stats over edges: y1 = p[dst] + q[src] + cb1 ----------------
__global__ void k_e1() {
    int tid = threadIdx.x;
    int l = tid >> 6, c = tid & 63;
    const int CH = NE / 512;   // 3125
    int start = blockIdx.x * CH, end = start + CH;
    float cb = g_cb1[c];
    float s = 0.f, ss = 0.f;
    for (int e = start + l; e < end; e += 4) {
        int d = g_dst[e], sr = g_src[e];
        float y = g_p[(size_t)d * EMBD + c] + g_q[(size_t)sr * EMBD + c] + cb;
        s += y; ss += y * y;
    }
    __shared__ float sh1[4][64], sh2[4][64];
    sh1[l][c] = s; sh2[l][c] = ss;
    __syncthreads();
    if (l == 0) {
        atomicAdd(&g_stats[c],      sh1[0][c] + sh1[1][c] + sh1[2][c] + sh1[3][c]);
        atomicAdd(&g_stats[64 + c], sh2[0][c] + sh2[1][c] + sh2[2][c] + sh2[3][c]);
    }
}

// ---------------- fold BN stats into per-channel (a, s) ----------------
__global__ void k_bn(int layer, float cnt, const float* gamma, const float* beta) {
    int c = threadIdx.x;
    float mu = g_stats[layer * 128 + c] / cnt;
    float v  = g_stats[layer * 128 + 64 + c] / cnt - mu * mu;
    float a  = gamma[c] * rsqrtf(fmaxf(v, 0.f) + EPSBN);
    g_bn[layer * 128 + c] = a;
    g_bn[layer * 128 + 64 + c] = beta[c] - mu * a;
}

// ---------------- shared 64x64 register-blocked GEMM core ----------------
__device__ __forceinline__ void tile_gemm(const float (*zs)[68], const float (*sw)[64],
                                          int r0, int c0, float acc[4][4]) {
#pragma unroll
    for (int k = 0; k < 64; k += 4) {
        float4 A0 = *(const float4*)&zs[r0 + 0][k];
        float4 A1 = *(const float4*)&zs[r0 + 1][k];
        float4 A2 = *(const float4*)&zs[r0 + 2][k];
        float4 A3 = *(const float4*)&zs[r0 + 3][k];
        const float* a0 = (const float*)&A0;
        const float* a1 = (const float*)&A1;
        const float* a2 = (const float*)&A2;
        const float* a3 = (const float*)&A3;
#pragma unroll
        for (int kk = 0; kk < 4; kk++) {
            float4 B = *(const float4*)&sw[k + kk][c0];
            acc[0][0] = fmaf(a0[kk], B.x, acc[0][0]);
            acc[0][1] = fmaf(a0[kk], B.y, acc[0][1]);
            acc[0][2] = fmaf(a0[kk], B.z, acc[0][2]);
            acc[0][3] = fmaf(a0[kk], B.w, acc[0][3]);
            acc[1][0] = fmaf(a1[kk], B.x, acc[1][0]);
            acc[1][1] = fmaf(a1[kk], B.y, acc[1][1]);
            acc[1][2] = fmaf(a1[kk], B.z, acc[1][2]);
            acc[1][3] = fmaf(a1[kk], B.w, acc[1][3]);
            acc[2][0] = fmaf(a2[kk], B.x, acc[2][0]);
            acc[2][1] = fmaf(a2[kk], B.y, acc[2][1]);
            acc[2][2] = fmaf(a2[kk], B.z, acc[2][2]);
            acc[2][3] = fmaf(a2[kk], B.w, acc[2][3]);
            acc[3][0] = fmaf(a3[kk], B.x, acc[3][0]);
            acc[3][1] = fmaf(a3[kk], B.y, acc[3][1]);
            acc[3][2] = fmaf(a3[kk], B.z, acc[3][2]);
            acc[3][3] = fmaf(a3[kk], B.w, acc[3][3]);
        }
    }
}

// stats reduction helper: per-thread 4-col partials -> block -> global atomics
__device__ __forceinline__ void tile_stats(float red[16][64], int ty, int c0,
                                           const float cs[4], const float cq[4],
                                           float* gsum, float* gsq) {
    int tid = threadIdx.x;
#pragma unroll
    for (int j = 0; j < 4; j++) red[ty][c0 + j] = cs[j];
    __syncthreads();
    if (tid < 64) {
        float t = 0.f;
#pragma unroll
        for (int y = 0; y < 16; y++) t += red[y][tid];
        atomicAdd(&gsum[tid], t);
    }
    __syncthreads();
#pragma unroll
    for (int j = 0; j < 4; j++) red[ty][c0 + j] = cq[j];
    __syncthreads();
    if (tid < 64) {
        float t = 0.f;
#pragma unroll
        for (int y = 0; y < 16; y++) t += red[y][tid];
        atomicAdd(&gsq[tid], t);
    }
}

// ---------------- edge layer 2: z = relu(bn1(y1)); y2 = z @ mW2 + mb2; stats2; store y2 ----------------
__global__ void __launch_bounds__(256) k_e2(const float* mW2, const float* mb2) {
    __shared__ __align__(16) float zs[64][68];
    __shared__ __align__(16) float sw[64][64];
    __shared__ float red[16][64];
    __shared__ int sd[64], ssr[64];
    int tid = threadIdx.x;
    int e0 = blockIdx.x * 64;
#pragma unroll
    for (int i = 0; i < 16; i++) { int idx = i * 256 + tid; sw[idx >> 6][idx & 63] = mW2[idx]; }
    if (tid < 64) { sd[tid] = g_dst[e0 + tid]; ssr[tid] = g_src[e0 + tid]; }
    __syncthreads();
    {
        int c = tid & 63, l = tid >> 6;
        float cb = g_cb1[c], a1 = g_bn[c], s1 = g_bn[64 + c];
#pragma unroll
        for (int j = 0; j < 16; j++) {
            int r = l + 4 * j;
            float y = g_p[(size_t)sd[r] * EMBD + c] + g_q[(size_t)ssr[r] * EMBD + c] + cb;
            zs[r][c] = fmaxf(fmaf(y, a1, s1), 0.f);
        }
    }
    __syncthreads();
    int tx = tid & 15, ty = tid >> 4;
    int c0 = tx * 4, r0 = ty * 4;
    float acc[4][4];
#pragma unroll
    for (int j = 0; j < 4; j++) {
        float b = mb2[c0 + j];
        acc[0][j] = b; acc[1][j] = b; acc[2][j] = b; acc[3][j] = b;
    }
    tile_gemm(zs, sw, r0, c0, acc);
    float cs[4] = {0, 0, 0, 0}, cq[4] = {0, 0, 0, 0};
#pragma unroll
    for (int i = 0; i < 4; i++) {
        float4 o; o.x = acc[i][0]; o.y = acc[i][1]; o.z = acc[i][2]; o.w = acc[i][3];
        *(float4*)&g_y2[(size_t)(e0 + r0 + i) * EMBD + c0] = o;
#pragma unroll
        for (int j = 0; j < 4; j++) { cs[j] += acc[i][j]; cq[j] += acc[i][j] * acc[i][j]; }
    }
    tile_stats(red, ty, c0, cs, cq, &g_stats[128], &g_stats[192]);
}

// ---------------- scatter: msg = relu(bn2(y2)); aggr[dst] += msg (float4 loads) ----------------
__global__ void k_e3() {
    size_t stride = (size_t)gridDim.x * blockDim.x;
    size_t total = (size_t)NE * (EMBD / 4);          // one float4 per thread-iter
    for (size_t i = (size_t)blockIdx.x * blockDim.x + threadIdx.x; i < total; i += stride) {
        int c4 = (int)(i & 15);                       // which float4 within the row
        size_t e = i >> 4;
        int c = c4 * 4;
        float4 v = *(const float4*)&g_y2[(e << 6) + c];
        float4 a = *(const float4*)&g_bn[128 + c];
        float4 s = *(const float4*)&g_bn[192 + c];
        float* dst = &g_aggr[(size_t)g_dst[e] * EMBD + c];
        atomicAdd(dst + 0, fmaxf(fmaf(v.x, a.x, s.x), 0.f));
        atomicAdd(dst + 1, fmaxf(fmaf(v.y, a.y, s.y), 0.f));
        atomicAdd(dst + 2, fmaxf(fmaf(v.z, a.z, s.z), 0.f));
        atomicAdd(dst + 3, fmaxf(fmaf(v.w, a.w, s.w), 0.f));
    }
}

// ---------------- node layer 1: y3 = x@Cu + aggr@uW1_bot + cbu; stats3; store y3 ----------------
__global__ void __launch_bounds__(256) k_u1(const float* pos, const float* vel, const float* uW1) {
    __shared__ __align__(16) float as_[64][68];
    __shared__ __align__(16) float sw[64][64];
    __shared__ float red[16][64];
    __shared__ float sx[64][4];
    int tid = threadIdx.x;
    int n0 = blockIdx.x * 64;
#pragma unroll
    for (int i = 0; i < 16; i++) { int idx = i * 256 + tid; sw[idx >> 6][idx & 63] = uW1[4096 + idx]; }
    if (tid < 64) {
        int n = n0 + tid;
        if (n < NN) {
            sx[tid][0] = pos[2 * n]; sx[tid][1] = pos[2 * n + 1];
            sx[tid][2] = vel[2 * n]; sx[tid][3] = vel[2 * n + 1];
        } else {
            sx[tid][0] = sx[tid][1] = sx[tid][2] = sx[tid][3] = 0.f;
        }
    }
    {
        int c = tid & 63, l = tid >> 6;
#pragma unroll
        for (int j = 0; j < 16; j++) {
            int r = l + 4 * j; int n = n0 + r;
            as_[r][c] = (n < NN) ? g_aggr[(size_t)n * EMBD + c] : 0.f;
        }
    }
    __syncthreads();
    int tx = tid & 15, ty = tid >> 4;
    int c0 = tx * 4, r0 = ty * 4;
    float acc[4][4];
#pragma unroll
    for (int i = 0; i < 4; i++) {
        int r = r0 + i;
#pragma unroll
        for (int j = 0; j < 4; j++) {
            int c = c0 + j;
            acc[i][j] = g_cbu[c] + sx[r][0] * g_Cu[c] + sx[r][1] * g_Cu[64 + c]
                      + sx[r][2] * g_Cu[128 + c] + sx[r][3] * g_Cu[192 + c];
        }
    }
    tile_gemm(as_, sw, r0, c0, acc);
    float cs[4] = {0, 0, 0, 0}, cq[4] = {0, 0, 0, 0};
#pragma unroll
    for (int i = 0; i < 4; i++) {
        int n = n0 + r0 + i;
        if (n < NN) {
            float4 o; o.x = acc[i][0]; o.y = acc[i][1]; o.z = acc[i][2]; o.w = acc[i][3];
            *(float4*)&g_y3[(size_t)n * EMBD + c0] = o;
#pragma unroll
            for (int j = 0; j < 4; j++) { cs[j] += acc[i][j]; cq[j] += acc[i][j] * acc[i][j]; }
        }
    }
    tile_stats(red, ty, c0, cs, cq, &g_stats[256], &g_stats[320]);
}

// ---------------- node layer 2: y4 = relu(bn3(y3)) @ uW2 + ub2; stats4; store y4 ----------------
__global__ void __launch_bounds__(256) k_u2(const float* uW2, const float* ub2) {
    __shared__ __align__(16) float as_[64][68];
    __shared__ __align__(16) float sw[64][64];
    __shared__ float red[16][64];
    int tid = threadIdx.x;
    int n0 = blockIdx.x * 64;
#pragma unroll
    for (int i = 0; i < 16; i++) { int idx = i * 256 + tid; sw[idx >> 6][idx & 63] = uW2[idx]; }
    {
        int c = tid & 63, l = tid >> 6;
        float a3 = g_bn[256 + c], s3 = g_bn[320 + c];
#pragma unroll
        for (int j = 0; j < 16; j++) {
            int r = l + 4 * j; int n = n0 + r;
            as_[r][c] = (n < NN) ? fmaxf(fmaf(g_y3[(size_t)n * EMBD + c], a3, s3), 0.f) : 0.f;
        }
    }
    __syncthreads();
    int tx = tid & 15, ty = tid >> 4;
    int c0 = tx * 4, r0 = ty * 4;
    float acc[4][4];
#pragma unroll
    for (int j = 0; j < 4; j++) {
        float b = ub2[c0 + j];
        acc[0][j] = b; acc[1][j] = b; acc[2][j] = b; acc[3][j] = b;
    }
    tile_gemm(as_, sw, r0, c0, acc);
    float cs[4] = {0, 0, 0, 0}, cq[4] = {0, 0, 0, 0};
#pragma unroll
    for (int i = 0; i < 4; i++) {
        int n = n0 + r0 + i;
        if (n < NN) {
            float4 o; o.x = acc[i][0]; o.y = acc[i][1]; o.z = acc[i][2]; o.w = acc[i][3];
            *(float4*)&g_y4[(size_t)n * EMBD + c0] = o;
#pragma unroll
            for (int j = 0; j < 4; j++) { cs[j] += acc[i][j]; cq[j] += acc[i][j] * acc[i][j]; }
        }
    }
    tile_stats(red, ty, c0, cs, cq, &g_stats[384], &g_stats[448]);
}

// ---------------- head: out = relu(bn4(y4)) @ W_pred + b_pred ----------------
__global__ void k_out(const float* Wp, const float* bp, float* out) {
    int w = threadIdx.x >> 5, lane = threadIdx.x & 31;
    int n = blockIdx.x * 8 + w;
    if (n >= NN) return;
    float v0 = g_y4[(size_t)n * EMBD + lane];
    float v1 = g_y4[(size_t)n * EMBD + 32 + lane];
    float u0 = fmaxf(fmaf(v0, g_bn[384 + lane], g_bn[448 + lane]), 0.f);
    float u1 = fmaxf(fmaf(v1, g_bn[384 + 32 + lane], g_bn[448 + 32 + lane]), 0.f);
    float t = u0 * Wp[lane] + u1 * Wp[32 + lane];
#pragma unroll
    for (int o = 16; o; o >>= 1) t += __shfl_down_sync(0xffffffff, t, o);
    if (lane == 0) out[n] = t + bp[0];
}

extern "C" void kernel_launch(void* const* d_in, const int* in_sizes, int n_in,
                              void* d_out, int out_size) {
    const float* pos  = (const float*)d_in[0];
    const float* vel  = (const float*)d_in[1];
    const void*  ei   = d_in[2];
    const float* W_in = (const float*)d_in[3];
    const float* b_in = (const float*)d_in[4];
    const float* mW1  = (const float*)d_in[5];
    const float* mb1  = (const float*)d_in[6];
    const float* mg1  = (const float*)d_in[7];
    const float* mB1  = (const float*)d_in[8];
    const float* mW2  = (const float*)d_in[9];
    const float* mb2  = (const float*)d_in[10];
    const float* mg2  = (const float*)d_in[11];
    const float* mB2  = (const float*)d_in[12];
    const float* uW1  = (const float*)d_in[13];
    const float* ub1  = (const float*)d_in[14];
    const float* ug1  = (const float*)d_in[15];
    const float* uB1  = (const float*)d_in[16];
    const float* uW2  = (const float*)d_in[17];
    const float* ub2  = (const float*)d_in[18];
    const float* ug2  = (const float*)d_in[19];
    const float* uB2  = (const float*)d_in[20];
    const float* Wp   = (const float*)d_in[21];
    const float* bp   = (const float*)d_in[22];
    float* out = (float*)d_out;
    (void)in_sizes; (void)n_in; (void)out_size;

    k_detect<<<1, 256>>>((const unsigned int*)ei);
    k_zero<<<25000, 256>>>();
    k_conv<<<(NE + 255) / 256, 256>>>(ei);
    k_pre<<<1, 256>>>(W_in, b_in, mW1, mb1, uW1, ub1);
    k_pq<<<(NN * EMBD + 255) / 256, 256>>>(pos, vel);
    k_e1<<<512, 256>>>();
    k_bn<<<1, 64>>>(0, (float)NE, mg1, mB1);
    k_e2<<<NE / 64, 256>>>(mW2, mb2);
    k_bn<<<1, 64>>>(1, (float)NE, mg2, mB2);
    k_e3<<<12500, 256>>>();
    k_u1<<<(NN + 63) / 64, 256>>>(pos, vel, uW1);
    k_bn<<<1, 64>>>(2, (float)NN, ug1, uB1);
    k_u2<<<(NN + 63) / 64, 256>>>(uW2, ub2);
    k_bn<<<1, 64>>>(3, (float)NN, ug2, uB2);
    k_out<<<(NN + 7) / 8, 256>>>(Wp, bp, out);
}